// round 13
// baseline (speedup 1.0000x reference)
#include <cuda_runtime.h>
#include <cuda_bf16.h>
#include <cstdint>

// Per-segment vocab histogram: 14 x 8-bit counts packed in two u64 per
// segment (.x = vocab 0-7, .y = vocab 8-13). Zero-initialized at module
// load; the mma kernel re-zeros rows it consumes, so every graph replay
// starts from zeros. Counts exact (max seg len << 255, fields never carry).
#define MAX_T_ (1 << 17)
__device__ ulonglong2 g_hist2[MAX_T_];

// Precomputed B fragments (emb as bf16 hi + bf16 residual lo), written by
// hist_kernel block 0 each replay. Columns are PERMUTED so that tile-pair
// (2u, 2u+1) gives lane (g,q) output columns 16u+4q .. 16u+4q+3 -> STG.128.
__device__ uint2 g_bHI[2][8][32];
__device__ uint2 g_bLO[2][8][32];

// pack two f32 -> bf16x2 ('lo' lands in the low 16 bits)
#define PACK_BF16X2(res, lo, hi) \
    asm("cvt.rn.bf16x2.f32 %0, %1, %2;" : "=r"(res) : "f"(hi), "f"(lo))

#define DP4A_ACC(res, a, acc) \
    asm("dp4a.u32.u32 %0, %1, %2, %3;" : "=r"(res) : "r"(a), "r"(0x01010101u), "r"(acc))

static __device__ __forceinline__ void mma_bf16(
    float& d0, float& d1, float& d2, float& d3,
    uint32_t a0, uint32_t a1, uint32_t a2, uint32_t a3,
    uint32_t b0, uint32_t b1)
{
    asm volatile(
        "mma.sync.aligned.m16n8k16.row.col.f32.bf16.bf16.f32 "
        "{%0,%1,%2,%3}, {%4,%5,%6,%7}, {%8,%9}, {%0,%1,%2,%3};"
        : "+f"(d0), "+f"(d1), "+f"(d2), "+f"(d3)
        : "r"(a0), "r"(a1), "r"(a2), "r"(a3), "r"(b0), "r"(b1));
}

// ---------------------------------------------------------------------------
// Kernel 1: histogram with packed-u64 run aggregation (16 chars/thread) +
// B-fragment precompute (block 0, first 64 threads).
__global__ void hist_kernel(const int4* __restrict__ seg4,
                            const int4* __restrict__ cidx4,
                            const int* __restrict__ seg,
                            const int* __restrict__ cidx,
                            const float* __restrict__ emb,
                            int nq16, int N) {
    // ---- B-fragment precompute (permuted columns for STG.128 stores) ----
    if (blockIdx.x == 0 && threadIdx.x < 64) {
        const int half = threadIdx.x >> 5;
        const int lane = threadIdx.x & 31;
        const int q = lane & 3, g = lane >> 2;
        const int k0 = 2 * q, k1 = 2 * q + 1, k2 = 2 * q + 8, k3 = 2 * q + 9;
#pragma unroll
        for (int j = 0; j < 8; ++j) {
            const int u = j >> 1, odd = j & 1;
            const int nin = 16 * u + 2 * g + 2 * odd - (g & 1);
            const int n = 64 * half + nin;
            float e0 = (k0 < 14) ? emb[k0 * 128 + n] : 0.f;
            float e1 = (k1 < 14) ? emb[k1 * 128 + n] : 0.f;
            float e2 = (k2 < 14) ? emb[k2 * 128 + n] : 0.f;
            float e3 = (k3 < 14) ? emb[k3 * 128 + n] : 0.f;
            uint32_t h0, h1;
            PACK_BF16X2(h0, e0, e1);
            PACK_BF16X2(h1, e2, e3);
            float r0 = e0 - __uint_as_float(h0 << 16);
            float r1 = e1 - __uint_as_float(h0 & 0xffff0000u);
            float r2 = e2 - __uint_as_float(h1 << 16);
            float r3 = e3 - __uint_as_float(h1 & 0xffff0000u);
            uint32_t l0, l1;
            PACK_BF16X2(l0, r0, r1);
            PACK_BF16X2(l1, r2, r3);
            g_bHI[half][j][lane] = make_uint2(h0, h1);
            g_bLO[half][j][lane] = make_uint2(l0, l1);
        }
    }

    const int i = blockIdx.x * blockDim.x + threadIdx.x;
    if (i < nq16) {
        int s_[16], c_[16];
#pragma unroll
        for (int v = 0; v < 4; ++v) {
            int4 s = seg4[4 * i + v];
            int4 c = cidx4[4 * i + v];
            s_[4 * v + 0] = s.x; s_[4 * v + 1] = s.y;
            s_[4 * v + 2] = s.z; s_[4 * v + 3] = s.w;
            c_[4 * v + 0] = c.x; c_[4 * v + 1] = c.y;
            c_[4 * v + 2] = c.z; c_[4 * v + 3] = c.w;
        }

        unsigned long long lo = 0ull, hi = 0ull;
        int cur = s_[0];
#pragma unroll
        for (int k = 0; k < 16; ++k) {
            if (s_[k] != cur) {               // flush completed run
                atomicAdd(&g_hist2[cur].x, lo);
                if (hi) atomicAdd(&g_hist2[cur].y, hi);
                lo = 0ull; hi = 0ull; cur = s_[k];
            }
            unsigned long long one = 1ull << ((c_[k] & 7) * 8);
            if (c_[k] < 8) lo += one; else hi += one;
        }
        atomicAdd(&g_hist2[cur].x, lo);
        if (hi) atomicAdd(&g_hist2[cur].y, hi);
    } else if (i == nq16) {                   // scalar tail
        for (int j = nq16 * 16; j < N; ++j) {
            int t = seg[j], c = cidx[j];
            unsigned long long one = 1ull << ((c & 7) * 8);
            if (c < 8) atomicAdd(&g_hist2[t].x, one);
            else       atomicAdd(&g_hist2[t].y, one);
        }
    }
}

// ---------------------------------------------------------------------------
// Build A-fragment halves + segment length from one packed hist row.
static __device__ __forceinline__ void row_frag(
    ulonglong2 r, int q, uint32_t& aL, uint32_t& aH, float& lenf)
{
    const unsigned sh = (unsigned)q * 16u;
    float f0 = (float)((uint32_t)(r.x >> sh) & 0xffu);
    float f1 = (float)((uint32_t)(r.x >> (sh + 8u)) & 0xffu);
    float f2 = (float)((uint32_t)(r.y >> sh) & 0xffu);
    float f3 = (float)((uint32_t)(r.y >> (sh + 8u)) & 0xffu);
    PACK_BF16X2(aL, f0, f1);
    PACK_BF16X2(aH, f2, f3);
    uint32_t w0 = (uint32_t)r.x, w1 = (uint32_t)(r.x >> 32);
    uint32_t w2 = (uint32_t)r.y, w3 = (uint32_t)(r.y >> 32);
    uint32_t len;
    DP4A_ACC(len, w0, 0u);
    DP4A_ACC(len, w1, len);
    DP4A_ACC(len, w2, len);
    DP4A_ACC(len, w3, len);
    lenf = (float)len;
}

// Process one 16-row m-tile: frags -> 16 MMAs -> 8 STG.128.
static __device__ __forceinline__ void do_mtile(
    ulonglong2 r0, ulonglong2 r1, int q,
    const uint32_t bhi[8][2], const uint32_t blo[8][2],
    float* __restrict__ po0, float* __restrict__ po1, bool ok0, bool ok1)
{
    uint32_t a0, a1, a2, a3;
    float len0, len1;
    row_frag(r0, q, a0, a2, len0);
    row_frag(r1, q, a1, a3, len1);
    const float s0 = __fdividef(1.0f, fmaxf(len0, 1.0f));
    const float s1 = __fdividef(1.0f, fmaxf(len1, 1.0f));

#pragma unroll
    for (int u = 0; u < 4; ++u) {
        float h0 = 0.f, h1 = 0.f, h2 = 0.f, h3 = 0.f;   // tile 2u hi
        float l0 = 0.f, l1 = 0.f, l2 = 0.f, l3 = 0.f;   // tile 2u lo
        float e0 = 0.f, e1 = 0.f, e2 = 0.f, e3 = 0.f;   // tile 2u+1 hi
        float m0 = 0.f, m1 = 0.f, m2 = 0.f, m3 = 0.f;   // tile 2u+1 lo
        mma_bf16(h0, h1, h2, h3, a0, a1, a2, a3, bhi[2*u][0],   bhi[2*u][1]);
        mma_bf16(l0, l1, l2, l3, a0, a1, a2, a3, blo[2*u][0],   blo[2*u][1]);
        mma_bf16(e0, e1, e2, e3, a0, a1, a2, a3, bhi[2*u+1][0], bhi[2*u+1][1]);
        mma_bf16(m0, m1, m2, m3, a0, a1, a2, a3, blo[2*u+1][0], blo[2*u+1][1]);
        if (ok0) *reinterpret_cast<float4*>(po0 + 16 * u + 4 * q) =
            make_float4((h0 + l0) * s0, (h1 + l1) * s0,
                        (e0 + m0) * s0, (e1 + m1) * s0);
        if (ok1) *reinterpret_cast<float4*>(po1 + 16 * u + 4 * q) =
            make_float4((h2 + l2) * s1, (h3 + l3) * s1,
                        (e2 + m2) * s1, (e3 + m3) * s1);
    }
}

// ---------------------------------------------------------------------------
// Kernel 2: warp-pair bf16 HMMA GEMM, STG.128 epilogue, single CTA barrier.
// All warps preload both m-tiles' hist rows, one __syncthreads orders the
// loads vs the coalesced CTA-wide clear (threads 0-127, 2KB contiguous),
// then both m-tiles are computed with no further synchronization.
__global__ void __launch_bounds__(256, 3)
mma_kernel(float* __restrict__ out, int T) {
    const int lane = threadIdx.x & 31;
    const int q    = lane & 3;
    const int g    = lane >> 2;
    const int half = (threadIdx.x >> 5) & 1;
    const int pair_in_blk = threadIdx.x >> 6;         // 0..3
    const int t_base = blockIdx.x * 128 + pair_in_blk * 32;

    // ---- B fragments: 16 coalesced LDG.64 from the precomputed buffer ----
    uint32_t bhi[8][2], blo[8][2];
#pragma unroll
    for (int j = 0; j < 8; ++j) {
        uint2 h = g_bHI[half][j][lane];
        uint2 l = g_bLO[half][j][lane];
        bhi[j][0] = h.x; bhi[j][1] = h.y;
        blo[j][0] = l.x; blo[j][1] = l.y;
    }

    const ulonglong2 zrow = make_ulonglong2(0ull, 0ull);

    // ---- preload both m-tiles' rows ----
    const int tA0 = t_base + g,      tA1 = t_base + g + 8;
    const int tB0 = t_base + g + 16, tB1 = t_base + g + 24;
    ulonglong2 rA0 = zrow, rA1 = zrow, rB0 = zrow, rB1 = zrow;
    if (tA0 < T) rA0 = g_hist2[tA0];
    if (tA1 < T) rA1 = g_hist2[tA1];
    if (tB0 < T) rB0 = g_hist2[tB0];
    if (tB1 < T) rB1 = g_hist2[tB1];

    // ---- one barrier: all pair loads done; then coalesced clear ----
    __syncthreads();
    {
        const int zr = blockIdx.x * 128 + threadIdx.x;
        if (threadIdx.x < 128 && zr < T) g_hist2[zr] = zrow;
    }

    // ---- m-tile A ----
    do_mtile(rA0, rA1, q, bhi, blo,
             out + (size_t)tA0 * 128 + 64 * half,
             out + (size_t)tA1 * 128 + 64 * half,
             tA0 < T, tA1 < T);
    // ---- m-tile B ----
    do_mtile(rB0, rB1, q, bhi, blo,
             out + (size_t)tB0 * 128 + 64 * half,
             out + (size_t)tB1 * 128 + 64 * half,
             tB0 < T, tB1 < T);
}

// ---------------------------------------------------------------------------
extern "C" void kernel_launch(void* const* d_in, const int* in_sizes, int n_in,
                              void* d_out, int out_size) {
    const float* char_emb     = (const float*)d_in[0];
    const int*   char_indices = (const int*)d_in[1];
    const int*   segment_ids  = (const int*)d_in[2];
    float*       out          = (float*)d_out;

    int N = in_sizes[1];          // total chars
    int T = out_size / 128;       // segments (d_model = 128)

    {   // histogram + B-fragment precompute: 16 chars/thread
        int nq16 = N >> 4;
        int threads = 256;
        int work = nq16 + 1;
        hist_kernel<<<(work + threads - 1) / threads, threads>>>(
            (const int4*)segment_ids, (const int4*)char_indices,
            segment_ids, char_indices, char_emb, nq16, N);
    }
    {   // HMMA GEMM: 128 segments per block
        int blocks = (T + 127) / 128;
        mma_kernel<<<blocks, 256>>>(out, T);
    }
}

// round 14
// speedup vs baseline: 1.0935x; 1.0935x over previous
#include <cuda_runtime.h>
#include <cuda_bf16.h>
#include <cstdint>

// Per-segment vocab histogram: 14 x 8-bit counts packed in two u64 per
// segment (.x = vocab 0-7, .y = vocab 8-13). Zero-initialized at module
// load; the mma kernel re-zeros rows it consumes, so every graph replay
// starts from zeros. Counts exact (max seg len << 255, fields never carry).
#define MAX_T_ (1 << 17)
__device__ ulonglong2 g_hist2[MAX_T_];

// Precomputed B fragments (emb as bf16 hi + bf16 residual lo), written by
// hist_kernel block 0 each replay. Columns are PERMUTED so that tile-pair
// (2u, 2u+1) gives lane (g,q) output columns 16u+4q .. 16u+4q+3 -> STG.128.
__device__ uint2 g_bHI[2][8][32];
__device__ uint2 g_bLO[2][8][32];

// pack two f32 -> bf16x2 ('lo' lands in the low 16 bits)
#define PACK_BF16X2(res, lo, hi) \
    asm("cvt.rn.bf16x2.f32 %0, %1, %2;" : "=r"(res) : "f"(hi), "f"(lo))

#define DP4A_ACC(res, a, acc) \
    asm("dp4a.u32.u32 %0, %1, %2, %3;" : "=r"(res) : "r"(a), "r"(0x01010101u), "r"(acc))

static __device__ __forceinline__ void mma_bf16(
    float& d0, float& d1, float& d2, float& d3,
    uint32_t a0, uint32_t a1, uint32_t a2, uint32_t a3,
    uint32_t b0, uint32_t b1)
{
    asm volatile(
        "mma.sync.aligned.m16n8k16.row.col.f32.bf16.bf16.f32 "
        "{%0,%1,%2,%3}, {%4,%5,%6,%7}, {%8,%9}, {%0,%1,%2,%3};"
        : "+f"(d0), "+f"(d1), "+f"(d2), "+f"(d3)
        : "r"(a0), "r"(a1), "r"(a2), "r"(a3), "r"(b0), "r"(b1));
}

// ---------------------------------------------------------------------------
// Kernel 1: histogram with packed-u64 run aggregation (8 chars/thread) +
// B-fragment precompute (block 0, first 64 threads). [R11 version — the
// 16-chars/thread variant lost MLP and regressed.]
__global__ void hist_kernel(const int4* __restrict__ seg4,
                            const int4* __restrict__ cidx4,
                            const int* __restrict__ seg,
                            const int* __restrict__ cidx,
                            const float* __restrict__ emb,
                            int nq8, int N) {
    // ---- B-fragment precompute (permuted columns for STG.128 stores) ----
    if (blockIdx.x == 0 && threadIdx.x < 64) {
        const int half = threadIdx.x >> 5;
        const int lane = threadIdx.x & 31;
        const int q = lane & 3, g = lane >> 2;
        const int k0 = 2 * q, k1 = 2 * q + 1, k2 = 2 * q + 8, k3 = 2 * q + 9;
#pragma unroll
        for (int j = 0; j < 8; ++j) {
            const int u = j >> 1, odd = j & 1;
            const int nin = 16 * u + 2 * g + 2 * odd - (g & 1);
            const int n = 64 * half + nin;
            float e0 = (k0 < 14) ? emb[k0 * 128 + n] : 0.f;
            float e1 = (k1 < 14) ? emb[k1 * 128 + n] : 0.f;
            float e2 = (k2 < 14) ? emb[k2 * 128 + n] : 0.f;
            float e3 = (k3 < 14) ? emb[k3 * 128 + n] : 0.f;
            uint32_t h0, h1;
            PACK_BF16X2(h0, e0, e1);
            PACK_BF16X2(h1, e2, e3);
            float r0 = e0 - __uint_as_float(h0 << 16);
            float r1 = e1 - __uint_as_float(h0 & 0xffff0000u);
            float r2 = e2 - __uint_as_float(h1 << 16);
            float r3 = e3 - __uint_as_float(h1 & 0xffff0000u);
            uint32_t l0, l1;
            PACK_BF16X2(l0, r0, r1);
            PACK_BF16X2(l1, r2, r3);
            g_bHI[half][j][lane] = make_uint2(h0, h1);
            g_bLO[half][j][lane] = make_uint2(l0, l1);
        }
    }

    const int i = blockIdx.x * blockDim.x + threadIdx.x;
    if (i < nq8) {
        int4 sa = seg4[2 * i], sb = seg4[2 * i + 1];
        int4 ca = cidx4[2 * i], cb = cidx4[2 * i + 1];
        int s_[8] = { sa.x, sa.y, sa.z, sa.w, sb.x, sb.y, sb.z, sb.w };
        int c_[8] = { ca.x, ca.y, ca.z, ca.w, cb.x, cb.y, cb.z, cb.w };

        unsigned long long lo = 0ull, hi = 0ull;
        int cur = s_[0];
#pragma unroll
        for (int k = 0; k < 8; ++k) {
            if (s_[k] != cur) {               // flush completed run
                atomicAdd(&g_hist2[cur].x, lo);
                if (hi) atomicAdd(&g_hist2[cur].y, hi);
                lo = 0ull; hi = 0ull; cur = s_[k];
            }
            unsigned long long one = 1ull << ((c_[k] & 7) * 8);
            if (c_[k] < 8) lo += one; else hi += one;
        }
        atomicAdd(&g_hist2[cur].x, lo);
        if (hi) atomicAdd(&g_hist2[cur].y, hi);
    } else if (i == nq8) {                    // scalar tail
        for (int j = nq8 * 8; j < N; ++j) {
            int t = seg[j], c = cidx[j];
            unsigned long long one = 1ull << ((c & 7) * 8);
            if (c < 8) atomicAdd(&g_hist2[t].x, one);
            else       atomicAdd(&g_hist2[t].y, one);
        }
    }
}

// ---------------------------------------------------------------------------
// Build A-fragment halves + segment length from one packed hist row.
static __device__ __forceinline__ void row_frag(
    ulonglong2 r, int q, uint32_t& aL, uint32_t& aH, float& lenf)
{
    const unsigned sh = (unsigned)q * 16u;
    float f0 = (float)((uint32_t)(r.x >> sh) & 0xffu);
    float f1 = (float)((uint32_t)(r.x >> (sh + 8u)) & 0xffu);
    float f2 = (float)((uint32_t)(r.y >> sh) & 0xffu);
    float f3 = (float)((uint32_t)(r.y >> (sh + 8u)) & 0xffu);
    PACK_BF16X2(aL, f0, f1);
    PACK_BF16X2(aH, f2, f3);
    uint32_t w0 = (uint32_t)r.x, w1 = (uint32_t)(r.x >> 32);
    uint32_t w2 = (uint32_t)r.y, w3 = (uint32_t)(r.y >> 32);
    uint32_t len;
    DP4A_ACC(len, w0, 0u);
    DP4A_ACC(len, w1, len);
    DP4A_ACC(len, w2, len);
    DP4A_ACC(len, w3, len);
    lenf = (float)len;
}

// Process one 16-row m-tile: frags -> 16 MMAs -> 8 STG.128.
static __device__ __forceinline__ void do_mtile(
    ulonglong2 r0, ulonglong2 r1, int q,
    const uint32_t bhi[8][2], const uint32_t blo[8][2],
    float* __restrict__ po0, float* __restrict__ po1, bool ok0, bool ok1)
{
    uint32_t a0, a1, a2, a3;
    float len0, len1;
    row_frag(r0, q, a0, a2, len0);
    row_frag(r1, q, a1, a3, len1);
    const float s0 = __fdividef(1.0f, fmaxf(len0, 1.0f));
    const float s1 = __fdividef(1.0f, fmaxf(len1, 1.0f));

#pragma unroll
    for (int u = 0; u < 4; ++u) {
        float h0 = 0.f, h1 = 0.f, h2 = 0.f, h3 = 0.f;   // tile 2u hi
        float l0 = 0.f, l1 = 0.f, l2 = 0.f, l3 = 0.f;   // tile 2u lo
        float e0 = 0.f, e1 = 0.f, e2 = 0.f, e3 = 0.f;   // tile 2u+1 hi
        float m0 = 0.f, m1 = 0.f, m2 = 0.f, m3 = 0.f;   // tile 2u+1 lo
        mma_bf16(h0, h1, h2, h3, a0, a1, a2, a3, bhi[2*u][0],   bhi[2*u][1]);
        mma_bf16(l0, l1, l2, l3, a0, a1, a2, a3, blo[2*u][0],   blo[2*u][1]);
        mma_bf16(e0, e1, e2, e3, a0, a1, a2, a3, bhi[2*u+1][0], bhi[2*u+1][1]);
        mma_bf16(m0, m1, m2, m3, a0, a1, a2, a3, blo[2*u+1][0], blo[2*u+1][1]);
        if (ok0) *reinterpret_cast<float4*>(po0 + 16 * u + 4 * q) =
            make_float4((h0 + l0) * s0, (h1 + l1) * s0,
                        (e0 + m0) * s0, (e1 + m1) * s0);
        if (ok1) *reinterpret_cast<float4*>(po1 + 16 * u + 4 * q) =
            make_float4((h2 + l2) * s1, (h3 + l3) * s1,
                        (e2 + m2) * s1, (e3 + m3) * s1);
    }
}

// ---------------------------------------------------------------------------
// Kernel 2: warp-pair bf16 HMMA GEMM, STG.128 epilogue, single CTA barrier.
// All warps preload both m-tiles' hist rows, one __syncthreads orders the
// loads vs the coalesced CTA-wide clear (threads 0-127, 2KB contiguous),
// then both m-tiles are computed with no further synchronization.
__global__ void __launch_bounds__(256, 3)
mma_kernel(float* __restrict__ out, int T) {
    const int lane = threadIdx.x & 31;
    const int q    = lane & 3;
    const int g    = lane >> 2;
    const int half = (threadIdx.x >> 5) & 1;
    const int pair_in_blk = threadIdx.x >> 6;         // 0..3
    const int t_base = blockIdx.x * 128 + pair_in_blk * 32;

    // ---- B fragments: 16 coalesced LDG.64 from the precomputed buffer ----
    uint32_t bhi[8][2], blo[8][2];
#pragma unroll
    for (int j = 0; j < 8; ++j) {
        uint2 h = g_bHI[half][j][lane];
        uint2 l = g_bLO[half][j][lane];
        bhi[j][0] = h.x; bhi[j][1] = h.y;
        blo[j][0] = l.x; blo[j][1] = l.y;
    }

    const ulonglong2 zrow = make_ulonglong2(0ull, 0ull);

    // ---- preload both m-tiles' rows ----
    const int tA0 = t_base + g,      tA1 = t_base + g + 8;
    const int tB0 = t_base + g + 16, tB1 = t_base + g + 24;
    ulonglong2 rA0 = zrow, rA1 = zrow, rB0 = zrow, rB1 = zrow;
    if (tA0 < T) rA0 = g_hist2[tA0];
    if (tA1 < T) rA1 = g_hist2[tA1];
    if (tB0 < T) rB0 = g_hist2[tB0];
    if (tB1 < T) rB1 = g_hist2[tB1];

    // ---- one barrier: all pair loads done; then coalesced clear ----
    __syncthreads();
    {
        const int zr = blockIdx.x * 128 + threadIdx.x;
        if (threadIdx.x < 128 && zr < T) g_hist2[zr] = zrow;
    }

    // ---- m-tile A ----
    do_mtile(rA0, rA1, q, bhi, blo,
             out + (size_t)tA0 * 128 + 64 * half,
             out + (size_t)tA1 * 128 + 64 * half,
             tA0 < T, tA1 < T);
    // ---- m-tile B ----
    do_mtile(rB0, rB1, q, bhi, blo,
             out + (size_t)tB0 * 128 + 64 * half,
             out + (size_t)tB1 * 128 + 64 * half,
             tB0 < T, tB1 < T);
}

// ---------------------------------------------------------------------------
extern "C" void kernel_launch(void* const* d_in, const int* in_sizes, int n_in,
                              void* d_out, int out_size) {
    const float* char_emb     = (const float*)d_in[0];
    const int*   char_indices = (const int*)d_in[1];
    const int*   segment_ids  = (const int*)d_in[2];
    float*       out          = (float*)d_out;

    int N = in_sizes[1];          // total chars
    int T = out_size / 128;       // segments (d_model = 128)

    {   // histogram + B-fragment precompute: 8 chars/thread
        int nq8 = N >> 3;
        int threads = 256;
        int work = nq8 + 1;
        hist_kernel<<<(work + threads - 1) / threads, threads>>>(
            (const int4*)segment_ids, (const int4*)char_indices,
            segment_ids, char_indices, char_emb, nq8, N);
    }
    {   // HMMA GEMM: 128 segments per block
        int blocks = (T + 127) / 128;
        mma_kernel<<<blocks, 256>>>(out, T);
    }
}